// round 12
// baseline (speedup 1.0000x reference)
#include <cuda_runtime.h>
#include <cstdint>

// out[p] = (L >= 0) || (missing(p) - L >= 0.5), written as float 0.0/1.0
// L = 7-point Laplacian (6*center - face neighbors, zero padding);
// missing(p) = count of out-of-grid face neighbors (kernel sums to 0 =>
// conv(1-m,k) = missing(p) - conv(m,k)).
//
// Two adjacent y-rows per thread (ya, yb=ya+1), rolling over z:
// the y-neighbors of ya/yb are each other's rolling center rows, so each
// iteration loads only 4 float4 (C0, C1, row ya-1, row yb+1) for 8 outputs.
// Compare form: g = 6*c vs s = sum(neighbors):
//   L >= 0        <=> g >= s
//   miss-L >= 0.5 <=> g <= s + (miss-0.5)
// x-halo via warp shuffle; __stcs streaming stores keep input L2-resident.

#define DSZ 192
#define KZ  4
#define ZT  (DSZ / KZ)   // 48 z-tiles

__global__ __launch_bounds__(384, 4) void mask_kernel(
    const float* __restrict__ m, float* __restrict__ out)
{
    const int tx = threadIdx.x;                       // 0..47 -> x quad
    const int ty = threadIdx.y;                       // 0..7  -> row pair
    const int ya = blockIdx.y * 16 + ty * 2;
    const int yb = ya + 1;
    const int zb = blockIdx.z;
    const int z0 = (zb % ZT) * KZ;
    const int b  = zb / ZT;
    const int x0 = tx * 4;
    const int lane = (ty * 48 + tx) & 31;

    const size_t plane = (size_t)DSZ * DSZ;
    const float* p0 = m + (((size_t)b * DSZ + z0) * DSZ + ya) * DSZ + x0;
    float* q0 = out + (((size_t)b * DSZ + z0) * DSZ + ya) * DSZ + x0;

    const float4 zero4 = make_float4(0.f, 0.f, 0.f, 0.f);
    const bool hasYm = (ya > 0);
    const bool hasYp = (yb < DSZ - 1);
    const bool hasXl = (x0 > 0);
    const bool hasXr = (x0 + 4 < DSZ);
    const bool edgeL = hasXl && (lane == 0);
    const bool edgeR = hasXr && (lane == 31);

    const float exl = hasXl ? 0.f : 1.f;
    const float exr = hasXr ? 0.f : 1.f;
    const float tba = (hasYm ? 0.f : 1.f) - 0.5f;   // row ya threshold base
    const float tbb = (hasYp ? 0.f : 1.f) - 0.5f;   // row yb threshold base

    float4 A0 = (z0 > 0) ? *(const float4*)(p0 - plane)       : zero4; // z-1, ya
    float4 A1 = (z0 > 0) ? *(const float4*)(p0 - plane + DSZ) : zero4; // z-1, yb
    float4 B0 = *(const float4*)(p0);                                   // z, ya
    float4 B1 = *(const float4*)(p0 + DSZ);                             // z, yb

    #pragma unroll
    for (int iz = 0; iz < KZ; ++iz) {
        const int z = z0 + iz;
        const bool hasZp = (z < DSZ - 1);
        float4 C0 = hasZp  ? *(const float4*)(p0 + plane)       : zero4;
        float4 C1 = hasZp  ? *(const float4*)(p0 + plane + DSZ) : zero4;
        float4 ym = hasYm ? *(const float4*)(p0 - DSZ)          : zero4; // ya-1
        float4 yp = hasYp ? *(const float4*)(p0 + 2 * DSZ)      : zero4; // yb+1

        // x-halo via shuffle of the rolling center rows
        float xl0s = __shfl_up_sync(0xffffffffu, B0.w, 1);
        float xr0s = __shfl_down_sync(0xffffffffu, B0.x, 1);
        float xl1s = __shfl_up_sync(0xffffffffu, B1.w, 1);
        float xr1s = __shfl_down_sync(0xffffffffu, B1.x, 1);
        float xl0 = 0.f, xr0 = 0.f, xl1 = 0.f, xr1 = 0.f;
        if (hasXl) {
            xl0 = edgeL ? __ldg(p0 - 1)       : xl0s;
            xl1 = edgeL ? __ldg(p0 + DSZ - 1) : xl1s;
        }
        if (hasXr) {
            xr0 = edgeR ? __ldg(p0 + 4)       : xr0s;
            xr1 = edgeR ? __ldg(p0 + DSZ + 4) : xr1s;
        }

        const float mz = (float)((int)(z == 0) + (int)(z == DSZ - 1));
        const float ta = tba + mz, tb = tbb + mz;

        // row ya: y-neighbors = ym, B1
        float s0 = (xl0  + B0.y) + (ym.x + B1.x) + (A0.x + C0.x);
        float s1 = (B0.x + B0.z) + (ym.y + B1.y) + (A0.y + C0.y);
        float s2 = (B0.y + B0.w) + (ym.z + B1.z) + (A0.z + C0.z);
        float s3 = (B0.z + xr0 ) + (ym.w + B1.w) + (A0.w + C0.w);
        float g0 = 6.f * B0.x, g1 = 6.f * B0.y, g2 = 6.f * B0.z, g3 = 6.f * B0.w;

        float4 oa;
        oa.x = ((g0 >= s0) | (g0 <= s0 + (ta + exl))) ? 1.f : 0.f;
        oa.y = ((g1 >= s1) | (g1 <= s1 + ta))         ? 1.f : 0.f;
        oa.z = ((g2 >= s2) | (g2 <= s2 + ta))         ? 1.f : 0.f;
        oa.w = ((g3 >= s3) | (g3 <= s3 + (ta + exr))) ? 1.f : 0.f;
        __stcs((float4*)q0, oa);

        // row yb: y-neighbors = B0, yp
        float u0 = (xl1  + B1.y) + (B0.x + yp.x) + (A1.x + C1.x);
        float u1 = (B1.x + B1.z) + (B0.y + yp.y) + (A1.y + C1.y);
        float u2 = (B1.y + B1.w) + (B0.z + yp.z) + (A1.z + C1.z);
        float u3 = (B1.z + xr1 ) + (B0.w + yp.w) + (A1.w + C1.w);
        float h0 = 6.f * B1.x, h1 = 6.f * B1.y, h2 = 6.f * B1.z, h3 = 6.f * B1.w;

        float4 ob;
        ob.x = ((h0 >= u0) | (h0 <= u0 + (tb + exl))) ? 1.f : 0.f;
        ob.y = ((h1 >= u1) | (h1 <= u1 + tb))         ? 1.f : 0.f;
        ob.z = ((h2 >= u2) | (h2 <= u2 + tb))         ? 1.f : 0.f;
        ob.w = ((h3 >= u3) | (h3 <= u3 + (tb + exr))) ? 1.f : 0.f;
        __stcs((float4*)(q0 + DSZ), ob);

        A0 = B0; A1 = B1; B0 = C0; B1 = C1;
        p0 += plane; q0 += plane;
    }
}

extern "C" void kernel_launch(void* const* d_in, const int* in_sizes, int n_in,
                              void* d_out, int out_size)
{
    const float* m = (const float*)d_in[0];
    float* out = (float*)d_out;

    dim3 block(48, 8, 1);                 // 384 threads: full row x 8 row-pairs
    dim3 grid(1, DSZ / 16, 2 * ZT);       // 12 y-tiles, (batch * 48 z-tiles)
    mask_kernel<<<grid, block>>>(m, out);
}

// round 13
// speedup vs baseline: 2.1262x; 2.1262x over previous
#include <cuda_runtime.h>
#include <cstdint>

// out[p] = (L >= 0) || (missing(p) - L >= 0.5), written as float 0.0/1.0
// L = 7-point Laplacian (6*center - face neighbors, zero padding);
// missing(p) = count of out-of-grid face neighbors (kernel sums to 0, so
// conv(1-m,k) = missing(p) - conv(m,k)).
//
// R10 (rolling-z x-quad, KZ=6, __stcs, shuffle x-halo) + 1-deep software
// prefetch of the z+1 plane: C for iteration iz+1 is loaded before the
// compute of iteration iz, hiding the ~250-cycle L2 latency behind a full
// iteration body. ym/yp stay as-is (L1 hits: adjacent ty threads load those
// lines as their centers). launch_bounds(384,4) gives the prefetch buffer
// register room.

#define DSZ 192
#define KZ  6
#define ZT  (DSZ / KZ)   // 32 z-tiles

__global__ __launch_bounds__(384, 4) void mask_kernel(
    const float* __restrict__ m, float* __restrict__ out)
{
    const int tx = threadIdx.x;                       // 0..47 -> x quad
    const int y  = blockIdx.y * blockDim.y + threadIdx.y;
    const int zb = blockIdx.z;
    const int z0 = (zb & (ZT - 1)) * KZ;
    const int b  = zb / ZT;
    const int x0 = tx * 4;
    const int lane = (threadIdx.y * 48 + tx) & 31;

    const size_t plane = (size_t)DSZ * DSZ;
    const float* p = m + (((size_t)b * DSZ + z0) * DSZ + y) * DSZ + x0;
    float* q = out + (((size_t)b * DSZ + z0) * DSZ + y) * DSZ + x0;

    const float4 zero4 = make_float4(0.f, 0.f, 0.f, 0.f);
    const bool hasYm = (y > 0);
    const bool hasYp = (y < DSZ - 1);
    const bool hasXl = (x0 > 0);
    const bool hasXr = (x0 + 4 < DSZ);
    const bool edgeL = hasXl && (lane == 0);
    const bool edgeR = hasXr && (lane == 31);
    const int  missY = (int)(!hasYm) + (int)(!hasYp);
    const float missE0 = (float)(missY + (int)(!hasXl));
    const float missE3 = (float)(missY + (int)(!hasXr));
    const float missM  = (float)missY;

    float4 A = (z0 > 0) ? *(const float4*)(p - plane) : zero4;  // z-1
    float4 B = *(const float4*)(p);                              // z
    float4 C = *(const float4*)(p + plane);                      // z+1 (z0+1<=187)

    #pragma unroll
    for (int iz = 0; iz < KZ; ++iz) {
        const int z = z0 + iz;

        // prefetch C for the NEXT iteration (plane z+2) before any compute
        float4 Cn = zero4;
        if (iz < KZ - 1) {
            if (z + 2 < DSZ) Cn = *(const float4*)(p + 2 * plane);
        }

        float4 ym = hasYm ? *(const float4*)(p - DSZ) : zero4;
        float4 yp = hasYp ? *(const float4*)(p + DSZ) : zero4;

        // x-halo via shuffle of the rolling center row
        float xls = __shfl_up_sync(0xffffffffu, B.w, 1);
        float xrs = __shfl_down_sync(0xffffffffu, B.x, 1);
        float xl = 0.f, xr = 0.f;
        if (hasXl) xl = edgeL ? __ldg(p - 1) : xls;
        if (hasXr) xr = edgeR ? __ldg(p + 4) : xrs;

        float L0 = 6.f * B.x - (xl  + B.y + ym.x + yp.x + A.x + C.x);
        float L1 = 6.f * B.y - (B.x + B.z + ym.y + yp.y + A.y + C.y);
        float L2 = 6.f * B.z - (B.y + B.w + ym.z + yp.z + A.z + C.z);
        float L3 = 6.f * B.w - (B.z + xr  + ym.w + yp.w + A.w + C.w);

        const float mz = (float)((int)(z == 0) + (int)(z == DSZ - 1));
        const float f0 = missE0 + mz;
        const float fm = missM  + mz;
        const float f3 = missE3 + mz;

        float4 o;
        o.x = ((L0 >= 0.f) || (f0 - L0 >= 0.5f)) ? 1.f : 0.f;
        o.y = ((L1 >= 0.f) || (fm - L1 >= 0.5f)) ? 1.f : 0.f;
        o.z = ((L2 >= 0.f) || (fm - L2 >= 0.5f)) ? 1.f : 0.f;
        o.w = ((L3 >= 0.f) || (f3 - L3 >= 0.5f)) ? 1.f : 0.f;

        __stcs((float4*)q, o);

        A = B; B = C; C = Cn;
        p += plane; q += plane;
    }
}

extern "C" void kernel_launch(void* const* d_in, const int* in_sizes, int n_in,
                              void* d_out, int out_size)
{
    const float* m = (const float*)d_in[0];
    float* out = (float*)d_out;

    dim3 block(48, 8, 1);                 // 384 threads: full row x 8 rows
    dim3 grid(1, DSZ / 8, 2 * ZT);        // y-tiles, (batch * z-tiles)
    mask_kernel<<<grid, block>>>(m, out);
}

// round 14
// speedup vs baseline: 2.2268x; 1.0473x over previous
#include <cuda_runtime.h>
#include <cstdint>

// out[p] = (L >= 0) || (missing(p) - L >= 0.5), written as float 0.0/1.0
// L = 7-point Laplacian (6*center - face neighbors, zero padding);
// missing(p) = count of out-of-grid face neighbors (kernel sums to 0, so
// conv(1-m,k) = missing(p) - conv(m,k)).
//
// R13 (rolling-z x-quad, __stcs, shuffle x-halo, 1-deep C prefetch) with:
//   - KZ=8: grid 1152 blocks = 1.95 waves at 4 CTAs/SM (vs 2.59 ragged)
//   - hoisted thresholds: z-boundary bump only materializes at iz==0 /
//     iz==KZ-1 in the unrolled loop; interior iterations use precomputed
//     constants (no per-iter int cmp/cvt/adds).

#define DSZ 192
#define KZ  8
#define ZT  (DSZ / KZ)   // 24 z-tiles

__global__ __launch_bounds__(384, 4) void mask_kernel(
    const float* __restrict__ m, float* __restrict__ out)
{
    const int tx = threadIdx.x;                       // 0..47 -> x quad
    const int y  = blockIdx.y * blockDim.y + threadIdx.y;
    const int zb = blockIdx.z;
    const int z0 = (zb % ZT) * KZ;
    const int b  = zb / ZT;
    const int x0 = tx * 4;
    const int lane = (threadIdx.y * 48 + tx) & 31;

    const size_t plane = (size_t)DSZ * DSZ;
    const float* p = m + (((size_t)b * DSZ + z0) * DSZ + y) * DSZ + x0;
    float* q = out + (((size_t)b * DSZ + z0) * DSZ + y) * DSZ + x0;

    const float4 zero4 = make_float4(0.f, 0.f, 0.f, 0.f);
    const bool hasYm = (y > 0);
    const bool hasYp = (y < DSZ - 1);
    const bool hasXl = (x0 > 0);
    const bool hasXr = (x0 + 4 < DSZ);
    const bool edgeL = hasXl && (lane == 0);
    const bool edgeR = hasXr && (lane == 31);

    // interior-z thresholds, precomputed once
    const float missY = (float)((int)(!hasYm) + (int)(!hasYp));
    const float f0i = missY + (float)(int)(!hasXl);
    const float fmi = missY;
    const float f3i = missY + (float)(int)(!hasXr);
    // z-boundary bumps (runtime 0/1, applied only at iz==0 / iz==KZ-1)
    const float mzFirst = (z0 == 0)        ? 1.f : 0.f;
    const float mzLast  = (z0 == DSZ - KZ) ? 1.f : 0.f;

    float4 A = (z0 > 0) ? *(const float4*)(p - plane) : zero4;  // z-1
    float4 B = *(const float4*)(p);                              // z
    float4 C = *(const float4*)(p + plane);                      // z+1 (<=185+... in-grid)

    #pragma unroll
    for (int iz = 0; iz < KZ; ++iz) {
        // prefetch C for the NEXT iteration (plane z+2) before any compute
        float4 Cn = zero4;
        if (iz < KZ - 1) {
            if (z0 + iz + 2 < DSZ) Cn = *(const float4*)(p + 2 * plane);
        }

        float4 ym = hasYm ? *(const float4*)(p - DSZ) : zero4;
        float4 yp = hasYp ? *(const float4*)(p + DSZ) : zero4;

        // x-halo via shuffle of the rolling center row
        float xls = __shfl_up_sync(0xffffffffu, B.w, 1);
        float xrs = __shfl_down_sync(0xffffffffu, B.x, 1);
        float xl = 0.f, xr = 0.f;
        if (hasXl) xl = edgeL ? __ldg(p - 1) : xls;
        if (hasXr) xr = edgeR ? __ldg(p + 4) : xrs;

        float L0 = 6.f * B.x - (xl  + B.y + ym.x + yp.x + A.x + C.x);
        float L1 = 6.f * B.y - (B.x + B.z + ym.y + yp.y + A.y + C.y);
        float L2 = 6.f * B.z - (B.y + B.w + ym.z + yp.z + A.z + C.z);
        float L3 = 6.f * B.w - (B.z + xr  + ym.w + yp.w + A.w + C.w);

        // compile-time folded for interior iterations (mzv == 0.0f constant)
        const float mzv = (iz == 0) ? mzFirst : ((iz == KZ - 1) ? mzLast : 0.f);
        const float f0 = f0i + mzv;
        const float fm = fmi + mzv;
        const float f3 = f3i + mzv;

        float4 o;
        o.x = ((L0 >= 0.f) || (f0 - L0 >= 0.5f)) ? 1.f : 0.f;
        o.y = ((L1 >= 0.f) || (fm - L1 >= 0.5f)) ? 1.f : 0.f;
        o.z = ((L2 >= 0.f) || (fm - L2 >= 0.5f)) ? 1.f : 0.f;
        o.w = ((L3 >= 0.f) || (fm - L3 >= 0.5f) || (f3 - L3 >= 0.5f)) ? 1.f : 0.f;

        __stcs((float4*)q, o);

        A = B; B = C; C = Cn;
        p += plane; q += plane;
    }
}

extern "C" void kernel_launch(void* const* d_in, const int* in_sizes, int n_in,
                              void* d_out, int out_size)
{
    const float* m = (const float*)d_in[0];
    float* out = (float*)d_out;

    dim3 block(48, 8, 1);                 // 384 threads: full row x 8 rows
    dim3 grid(1, DSZ / 8, 2 * ZT);        // y-tiles, (batch * z-tiles) = 1152
    mask_kernel<<<grid, block>>>(m, out);
}

// round 15
// speedup vs baseline: 2.3534x; 1.0569x over previous
#include <cuda_runtime.h>
#include <cstdint>

// out[p] = (L >= 0) || (missing(p) - L >= 0.5), written as float 0.0/1.0
// L = 7-point Laplacian (6*center - face neighbors, zero padding);
// missing(p) = count of out-of-grid face neighbors (kernel sums to 0, so
// conv(1-m,k) = missing(p) - conv(m,k)).
//
// R14 (rolling-z x-quad, __stcs, shuffle x-halo, 1-deep C prefetch,
// hoisted thresholds) with KZ=16: grid = 576 blocks <= 592 concurrent
// CTA slots (148 SMs x 4 CTAs) -> exactly ONE wave, no wave transition,
// no second-wave latency ramp.

#define DSZ 192
#define KZ  16
#define ZT  (DSZ / KZ)   // 12 z-tiles

__global__ __launch_bounds__(384, 4) void mask_kernel(
    const float* __restrict__ m, float* __restrict__ out)
{
    const int tx = threadIdx.x;                       // 0..47 -> x quad
    const int y  = blockIdx.y * blockDim.y + threadIdx.y;
    const int zb = blockIdx.z;
    const int z0 = (zb % ZT) * KZ;
    const int b  = zb / ZT;
    const int x0 = tx * 4;
    const int lane = (threadIdx.y * 48 + tx) & 31;

    const size_t plane = (size_t)DSZ * DSZ;
    const float* p = m + (((size_t)b * DSZ + z0) * DSZ + y) * DSZ + x0;
    float* q = out + (((size_t)b * DSZ + z0) * DSZ + y) * DSZ + x0;

    const float4 zero4 = make_float4(0.f, 0.f, 0.f, 0.f);
    const bool hasYm = (y > 0);
    const bool hasYp = (y < DSZ - 1);
    const bool hasXl = (x0 > 0);
    const bool hasXr = (x0 + 4 < DSZ);
    const bool edgeL = hasXl && (lane == 0);
    const bool edgeR = hasXr && (lane == 31);

    // interior-z thresholds, precomputed once
    const float missY = (float)((int)(!hasYm) + (int)(!hasYp));
    const float f0i = missY + (float)(int)(!hasXl);
    const float fmi = missY;
    const float f3i = missY + (float)(int)(!hasXr);
    // z-boundary bumps (applied only at iz==0 / iz==KZ-1)
    const float mzFirst = (z0 == 0)        ? 1.f : 0.f;
    const float mzLast  = (z0 == DSZ - KZ) ? 1.f : 0.f;

    float4 A = (z0 > 0) ? *(const float4*)(p - plane) : zero4;  // z-1
    float4 B = *(const float4*)(p);                              // z
    float4 C = *(const float4*)(p + plane);                      // z+1 (in-grid)

    #pragma unroll
    for (int iz = 0; iz < KZ; ++iz) {
        // prefetch C for the NEXT iteration (plane z+2) before any compute
        float4 Cn = zero4;
        if (iz < KZ - 1) {
            if (z0 + iz + 2 < DSZ) Cn = *(const float4*)(p + 2 * plane);
        }

        float4 ym = hasYm ? *(const float4*)(p - DSZ) : zero4;
        float4 yp = hasYp ? *(const float4*)(p + DSZ) : zero4;

        // x-halo via shuffle of the rolling center row
        float xls = __shfl_up_sync(0xffffffffu, B.w, 1);
        float xrs = __shfl_down_sync(0xffffffffu, B.x, 1);
        float xl = 0.f, xr = 0.f;
        if (hasXl) xl = edgeL ? __ldg(p - 1) : xls;
        if (hasXr) xr = edgeR ? __ldg(p + 4) : xrs;

        float L0 = 6.f * B.x - (xl  + B.y + ym.x + yp.x + A.x + C.x);
        float L1 = 6.f * B.y - (B.x + B.z + ym.y + yp.y + A.y + C.y);
        float L2 = 6.f * B.z - (B.y + B.w + ym.z + yp.z + A.z + C.z);
        float L3 = 6.f * B.w - (B.z + xr  + ym.w + yp.w + A.w + C.w);

        // compile-time folded for interior iterations (mzv == 0.0f constant)
        const float mzv = (iz == 0) ? mzFirst : ((iz == KZ - 1) ? mzLast : 0.f);
        const float f0 = f0i + mzv;
        const float fm = fmi + mzv;
        const float f3 = f3i + mzv;

        float4 o;
        o.x = ((L0 >= 0.f) || (f0 - L0 >= 0.5f)) ? 1.f : 0.f;
        o.y = ((L1 >= 0.f) || (fm - L1 >= 0.5f)) ? 1.f : 0.f;
        o.z = ((L2 >= 0.f) || (fm - L2 >= 0.5f)) ? 1.f : 0.f;
        o.w = ((L3 >= 0.f) || (f3 - L3 >= 0.5f)) ? 1.f : 0.f;

        __stcs((float4*)q, o);

        A = B; B = C; C = Cn;
        p += plane; q += plane;
    }
}

extern "C" void kernel_launch(void* const* d_in, const int* in_sizes, int n_in,
                              void* d_out, int out_size)
{
    const float* m = (const float*)d_in[0];
    float* out = (float*)d_out;

    dim3 block(48, 8, 1);                 // 384 threads: full row x 8 rows
    dim3 grid(1, DSZ / 8, 2 * ZT);        // y-tiles, (batch * z-tiles) = 576
    mask_kernel<<<grid, block>>>(m, out);
}